// round 10
// baseline (speedup 1.0000x reference)
#include <cuda_runtime.h>
#include <cuda_bf16.h>
#include <stdint.h>

#define WS 7
#define DROP_PROB 0.1f
#define H 256
#define W 256
#define HC (H - WS + 1)   // 250
#define WC (W - WS + 1)   // 250
#define BC (16 * 64)      // batch * channels = 1024
#define N4 (BC * H * W / 4)          // 16,777,216 float4 total
#define WORDS_PER_ROW 8              // 256 cols / 32 bits

#define BLOCKS 16384
#define THREADS 256
#define STRIDE (BLOCKS * THREADS)    // 4,194,304 — multiple of 16384
#define KITERS (N4 / STRIDE)         // 4

// ---------------------------------------------------------------------------
// Fused kernel, v2. Same structure as R9 (per-block iteration-invariant mask
// window over 4 image rows, built via ballots + 64-bit bit-smear), with two
// streaming-loop fixes driven by the R9 profile (alu=35%, regs=29 => loads
// not batched):
//   (a) the drop nibble is converted ONCE to a float4 multiplier, so the
//       loop body is pure FMUL (no per-iter LOP/ISETP/SEL);
//   (b) all KITERS loads are issued back-to-back into registers before any
//       compute/store, making MLP_p1 = 4 for latency hiding.
// ---------------------------------------------------------------------------
__global__ void __launch_bounds__(THREADS) fused_dropout_kernel(
        const float4* __restrict__ x, float4* __restrict__ out,
        const float* __restrict__ u) {
    __shared__ uint32_t hd[10][WORDS_PER_ROW];   // dilated anchor rows

    int tid  = threadIdx.x;
    int lane = tid & 31;
    int warp = tid >> 5;

    int base = blockIdx.x * THREADS;             // 256-aligned
    int L    = base & (H * W / 4 - 1);           // local float4 window start
    int r0   = L >> 6;                           // first of 4 pixel rows

    int a_start = r0 - (WS - 1); if (a_start < 0) a_start = 0;
    int a_end   = r0 + 3;        if (a_end > HC - 1) a_end = HC - 1;
    int nrows   = a_end - a_start + 1;           // <= 10

    // Phase 1: ballots + horizontal smear. Warp w covers relative rows w, w+8.
    #pragma unroll
    for (int pass = 0; pass < 2; ++pass) {
        int rr = warp + (pass << 3);             // 0..7, 8..15
        if (rr < nrows) {
            const float* __restrict__ urow = u + (a_start + rr) * WC;
            uint32_t dec[WORDS_PER_ROW];
            #pragma unroll
            for (int w = 0; w < WORDS_PER_ROW; ++w) {
                int col = (w << 5) + lane;
                bool pred = (col < WC) && (urow[col] < DROP_PROB);
                dec[w] = __ballot_sync(0xFFFFFFFFu, pred);  // uniform in warp
            }
            if (lane < WORDS_PER_ROW) {
                uint32_t hi = dec[0], lo = 0u;
                #pragma unroll
                for (int w = 0; w < WORDS_PER_ROW; ++w)
                    if (lane == w) { hi = dec[w]; lo = (w == 0) ? 0u : dec[w - 1]; }
                uint64_t v = ((uint64_t)hi << 32) | (uint64_t)lo;
                v |= v << 1;   // smear left by 6 total:
                v |= v << 2;   //   1+2+3 covers shifts 0..6
                v |= v << 3;
                hd[rr][lane] = (uint32_t)(v >> 32);
            }
        }
    }
    __syncthreads();

    // Phase 2: per-thread nibble -> float4 multiplier (computed ONCE).
    int row  = r0 + (tid >> 6);                  // this thread's pixel row
    int colw = tid & 63;                         // float4 column 0..63
    int wa0  = row - (WS - 1); if (wa0 < a_start) wa0 = a_start;
    int wa1  = row;            if (wa1 > a_end)   wa1 = a_end;
    uint32_t word = 0;
    for (int a = wa0; a <= wa1; ++a)
        word |= hd[a - a_start][colw >> 3];
    uint32_t nib = (word >> ((colw & 7) << 2)) & 0xFu;

    float4 m;
    m.x = (nib & 1u) ? 0.0f : 1.0f;
    m.y = (nib & 2u) ? 0.0f : 1.0f;
    m.z = (nib & 4u) ? 0.0f : 1.0f;
    m.w = (nib & 8u) ? 0.0f : 1.0f;

    // Phase 3: batched stream — 4 loads first (MLP=4), then 4 mul+stores.
    int i0 = base + tid;
    float4 xv[KITERS];
    #pragma unroll
    for (int k = 0; k < KITERS; ++k)
        xv[k] = x[i0 + k * STRIDE];

    #pragma unroll
    for (int k = 0; k < KITERS; ++k) {
        float4 ov;
        ov.x = xv[k].x * m.x;
        ov.y = xv[k].y * m.y;
        ov.z = xv[k].z * m.z;
        ov.w = xv[k].w * m.w;
        out[i0 + k * STRIDE] = ov;
    }
}

extern "C" void kernel_launch(void* const* d_in, const int* in_sizes, int n_in,
                              void* d_out, int out_size) {
    const float* x = (const float*)d_in[0];   // [16, 64, 256, 256] fp32
    const float* u = (const float*)d_in[1];   // [250, 250] fp32
    float* out = (float*)d_out;

    fused_dropout_kernel<<<BLOCKS, THREADS>>>(
        reinterpret_cast<const float4*>(x),
        reinterpret_cast<float4*>(out), u);
}